// round 2
// baseline (speedup 1.0000x reference)
#include <cuda_runtime.h>
#include <string.h>

#define S_LEN 512
#define B_SZ  256
#define DIN   64
#define H_DIM 256
#define MLPH  64
#define DOUT  16
#define KR    128            // W_hh columns held in registers per thread
#define KS    (H_DIM - KR)   // W_hh columns held in shared memory

// 134MB scratch for precomputed input projections: pre[t][b][j]
__device__ float g_pre[(size_t)S_LEN * B_SZ * H_DIM];

// Packed f32x2 FMA: d = a*b + c (per-lane fp32 fma, 2 MACs/instr)
__device__ __forceinline__ float2 ffma2(float2 a, float2 b, float2 c) {
    unsigned long long ua, ub, uc, ur;
    memcpy(&ua, &a, 8); memcpy(&ub, &b, 8); memcpy(&uc, &c, 8);
    asm("fma.rn.f32x2 %0, %1, %2, %3;" : "=l"(ur) : "l"(ua), "l"(ub), "l"(uc));
    float2 r; memcpy(&r, &ur, 8);
    return r;
}

// prediction_start arrives as a 1-element tensor; hedge against float32 encoding.
__device__ __forceinline__ int read_ps(const int* p) {
    int v = p[0];
    if (v < 0 || v > 1000000) v = (int)__int_as_float(v);
    return v;
}

// ---------------------------------------------------------------------------
// Pass 1: pre[t][b][j] = sum_k x[b][t][k] * W_ih[j][k] + b_ih[j] + b_hh[j]
// For t > ps only columns k in [16,64) contribute (first 16 are autoregressive).
// ---------------------------------------------------------------------------
__global__ void __launch_bounds__(256) precompute_kernel(
    const float* __restrict__ x, const float* __restrict__ W_ih,
    const float* __restrict__ b_ih, const float* __restrict__ b_hh,
    const int* __restrict__ psp)
{
    __shared__ float xs[32][DIN];
    const int t   = blockIdx.y;
    const int b0  = blockIdx.x * 32;
    const int tid = threadIdx.x;
    const int j   = tid;

    for (int idx = tid; idx < 32 * DIN; idx += 256) {
        int r = idx >> 6, k = idx & 63;
        xs[r][k] = x[((size_t)(b0 + r) * S_LEN + t) * DIN + k];
    }

    float2 wreg[DIN / 2];
    {
        const float2* wrow = reinterpret_cast<const float2*>(W_ih + (size_t)j * DIN);
        #pragma unroll
        for (int i = 0; i < DIN / 2; i++) wreg[i] = wrow[i];
    }
    const float bias = b_ih[j] + b_hh[j];
    const int ps = read_ps(psp);
    const bool full = (t <= ps);
    __syncthreads();

    for (int b = 0; b < 32; b++) {
        const float2* xb = reinterpret_cast<const float2*>(xs[b]);
        float2 acc = make_float2(bias, 0.f);
        #pragma unroll
        for (int i = 8; i < DIN / 2; i++) acc = ffma2(wreg[i], xb[i], acc);
        if (full) {
            #pragma unroll
            for (int i = 0; i < 8; i++) acc = ffma2(wreg[i], xb[i], acc);
        }
        g_pre[((size_t)t * B_SZ + (b0 + b)) * H_DIM + j] = acc.x + acc.y;
    }
}

// ---------------------------------------------------------------------------
// Pass 2: persistent recurrence. 128 blocks x 256 threads, 2 batch rows/block.
// Thread j owns hidden unit j. W_hh cols [0,128) in regs, [128,256) in smem.
// ---------------------------------------------------------------------------
struct SmemLayout {
    float2 whh2[KS / 2][H_DIM];    // 131072 B : (W_hh[j][128+2i], W_hh[j][129+2i]) at [i][j]
    float2 w1p [H_DIM / 2][MLPH];  //  65536 B : (W1[m][2i], W1[m][2i+1]) at [i][m]
    float2 w2p [MLPH / 2][MLPH];   //  16384 B
    float  w3t [MLPH][DOUT];       //   4096 B : W3[m][k] transposed -> [k][m]
    float  hp  [2][2][H_DIM];      //   4096 B : double-buffered hidden state
    float  red [2][4][MLPH];       //   2048 B : MLP1 partial sums
    float  h1s [2][MLPH];          //    512 B
    float  h2s [2][MLPH];          //    512 B
    float  o_sm[2][DOUT];          //    128 B : previous output (AR feedback)
    float  b1s[MLPH], b2s[MLPH], b3s[DOUT];
};

__global__ void __launch_bounds__(256, 1) rnn_kernel(
    const float* __restrict__ W_hh, const float* __restrict__ W_ih,
    const float* __restrict__ W1, const float* __restrict__ b1,
    const float* __restrict__ W2, const float* __restrict__ b2,
    const float* __restrict__ W3, const float* __restrict__ b3,
    const int* __restrict__ psp, float* __restrict__ out)
{
    extern __shared__ char smraw[];
    SmemLayout& sm = *reinterpret_cast<SmemLayout*>(smraw);
    const int tid = threadIdx.x;
    const int j   = tid;
    const int b0  = blockIdx.x * 2;
    const int ps  = read_ps(psp);

    // Register-resident weights: W_hh row j cols [0,128), W_ih row j cols [0,16)
    float2 wr[KR / 2];
    {
        const float2* row = reinterpret_cast<const float2*>(W_hh + (size_t)j * H_DIM);
        #pragma unroll
        for (int i = 0; i < KR / 2; i++) wr[i] = row[i];
    }
    float2 wa[DOUT / 2];
    {
        const float2* row = reinterpret_cast<const float2*>(W_ih + (size_t)j * DIN);
        #pragma unroll
        for (int i = 0; i < DOUT / 2; i++) wa[i] = row[i];
    }

    // Shared-memory weight staging (one-time)
    for (int idx = tid; idx < (KS / 2) * H_DIM; idx += 256) {
        int i = idx >> 8, jj = idx & (H_DIM - 1);
        sm.whh2[i][jj] = reinterpret_cast<const float2*>(W_hh + (size_t)jj * H_DIM + KR)[i];
    }
    for (int idx = tid; idx < (H_DIM / 2) * MLPH; idx += 256) {
        int i = idx >> 6, m = idx & 63;
        sm.w1p[i][m] = reinterpret_cast<const float2*>(W1 + (size_t)m * H_DIM)[i];
    }
    for (int idx = tid; idx < (MLPH / 2) * MLPH; idx += 256) {
        int i = idx >> 6, m = idx & 63;
        sm.w2p[i][m] = reinterpret_cast<const float2*>(W2 + (size_t)m * MLPH)[i];
    }
    for (int idx = tid; idx < MLPH * DOUT; idx += 256) {
        int k = idx >> 4, m = idx & 15;
        sm.w3t[k][m] = W3[(size_t)m * MLPH + k];
    }
    if (tid < MLPH) { sm.b1s[tid] = b1[tid]; sm.b2s[tid] = b2[tid]; }
    if (tid < DOUT) sm.b3s[tid] = b3[tid];
    sm.hp[0][0][tid] = 0.f;
    sm.hp[0][1][tid] = 0.f;
    if (tid < 2 * DOUT) sm.o_sm[tid >> 4][tid & 15] = 0.f;
    __syncthreads();

    // Prefetch pre for t=0
    float pn0 = g_pre[((size_t)0 * B_SZ + b0) * H_DIM + j];
    float pn1 = g_pre[((size_t)0 * B_SZ + b0 + 1) * H_DIM + j];

    int cur = 0;
    for (int t = 0; t < S_LEN; t++) {
        const float p0 = pn0, p1 = pn1;
        if (t + 1 < S_LEN) {
            pn0 = g_pre[((size_t)(t + 1) * B_SZ + b0) * H_DIM + j];
            pn1 = g_pre[((size_t)(t + 1) * B_SZ + b0 + 1) * H_DIM + j];
        }

        // ---- hidden update: h' = tanh(pre + [AR] + W_hh @ h) ----
        float2 a0 = make_float2(p0, 0.f), a1 = make_float2(p1, 0.f);
        if (t > ps) {
            const float2* o0 = reinterpret_cast<const float2*>(sm.o_sm[0]);
            const float2* o1 = reinterpret_cast<const float2*>(sm.o_sm[1]);
            #pragma unroll
            for (int i = 0; i < DOUT / 2; i++) {
                a0 = ffma2(wa[i], o0[i], a0);
                a1 = ffma2(wa[i], o1[i], a1);
            }
        }
        const float2* h0 = reinterpret_cast<const float2*>(sm.hp[cur][0]);
        const float2* h1v = reinterpret_cast<const float2*>(sm.hp[cur][1]);
        #pragma unroll
        for (int i = 0; i < KR / 2; i++) {
            float2 hh0 = h0[i], hh1 = h1v[i];
            a0 = ffma2(wr[i], hh0, a0);
            a1 = ffma2(wr[i], hh1, a1);
        }
        #pragma unroll 8
        for (int i = 0; i < KS / 2; i++) {
            float2 w = sm.whh2[i][j];
            a0 = ffma2(w, h0[KR / 2 + i], a0);
            a1 = ffma2(w, h1v[KR / 2 + i], a1);
        }
        const float hn0 = tanhf(a0.x + a0.y);
        const float hn1 = tanhf(a1.x + a1.y);
        const int nxt = cur ^ 1;
        sm.hp[nxt][0][j] = hn0;
        sm.hp[nxt][1][j] = hn1;
        __syncthreads();

        // ---- MLP layer 1: 64 outputs x 4 k-chunks across 256 threads ----
        {
            const int m = tid & 63, c = tid >> 6;
            const float2* g0 = reinterpret_cast<const float2*>(sm.hp[nxt][0]);
            const float2* g1 = reinterpret_cast<const float2*>(sm.hp[nxt][1]);
            float2 s0 = make_float2(0.f, 0.f), s1 = make_float2(0.f, 0.f);
            #pragma unroll
            for (int ii = 0; ii < 32; ii++) {
                const int i = c * 32 + ii;
                float2 w = sm.w1p[i][m];
                s0 = ffma2(w, g0[i], s0);
                s1 = ffma2(w, g1[i], s1);
            }
            sm.red[0][c][m] = s0.x + s0.y;
            sm.red[1][c][m] = s1.x + s1.y;
        }
        __syncthreads();
        if (tid < 128) {
            const int b = tid >> 6, m = tid & 63;
            float s = sm.red[b][0][m] + sm.red[b][1][m] + sm.red[b][2][m] +
                      sm.red[b][3][m] + sm.b1s[m];
            sm.h1s[b][m] = fmaxf(s, 0.f);
        }
        __syncthreads();

        // ---- MLP layer 2 ----
        if (tid < 128) {
            const int b = tid >> 6, m = tid & 63;
            const float2* g = reinterpret_cast<const float2*>(sm.h1s[b]);
            float2 acc = make_float2(0.f, 0.f);
            #pragma unroll
            for (int i = 0; i < MLPH / 2; i++) acc = ffma2(sm.w2p[i][m], g[i], acc);
            sm.h2s[b][m] = fmaxf(acc.x + acc.y + sm.b2s[m], 0.f);
        }
        __syncthreads();

        // ---- MLP layer 3 + output store + AR feedback ----
        if (tid < 32) {
            const int b = tid >> 4, m = tid & 15;
            float acc = sm.b3s[m];
            #pragma unroll
            for (int k = 0; k < MLPH; k++) acc += sm.w3t[k][m] * sm.h2s[b][k];
            sm.o_sm[b][m] = acc;
            out[((size_t)(b0 + b) * S_LEN + t) * DOUT + m] = acc;
        }
        cur = nxt;
        __syncthreads();
    }
}

extern "C" void kernel_launch(void* const* d_in, const int* in_sizes, int n_in,
                              void* d_out, int out_size) {
    const float* x    = (const float*)d_in[0];
    const float* W_ih = (const float*)d_in[1];
    const float* b_ih = (const float*)d_in[2];
    const float* W_hh = (const float*)d_in[3];
    const float* b_hh = (const float*)d_in[4];
    const float* W1   = (const float*)d_in[5];
    const float* b1   = (const float*)d_in[6];
    const float* W2   = (const float*)d_in[7];
    const float* b2   = (const float*)d_in[8];
    const float* W3   = (const float*)d_in[9];
    const float* b3   = (const float*)d_in[10];
    const int*   ps   = (const int*)d_in[11];
    float* out = (float*)d_out;

    precompute_kernel<<<dim3(B_SZ / 32, S_LEN), 256>>>(x, W_ih, b_ih, b_hh, ps);

    static_assert(sizeof(SmemLayout) <= 232448, "smem over budget");
    cudaFuncSetAttribute(rnn_kernel, cudaFuncAttributeMaxDynamicSharedMemorySize,
                         (int)sizeof(SmemLayout));
    rnn_kernel<<<B_SZ / 2, 256, sizeof(SmemLayout)>>>(
        W_hh, W_ih, W1, b1, W2, b2, W3, b3, ps, out);
}

// round 3
// speedup vs baseline: 1.2737x; 1.2737x over previous
#include <cuda_runtime.h>
#include <string.h>

#define S_LEN 512
#define B_SZ  256
#define DIN   64
#define H_DIM 256
#define MLPH  64
#define DOUT  16

// 134MB scratch for precomputed input projections: pre[t][b][j]
__device__ float g_pre[(size_t)S_LEN * B_SZ * H_DIM];

__device__ __forceinline__ float2 ffma2(float2 a, float2 b, float2 c) {
    unsigned long long ua, ub, uc, ur;
    memcpy(&ua, &a, 8); memcpy(&ub, &b, 8); memcpy(&uc, &c, 8);
    asm("fma.rn.f32x2 %0, %1, %2, %3;" : "=l"(ur) : "l"(ua), "l"(ub), "l"(uc));
    float2 r; memcpy(&r, &ur, 8);
    return r;
}
__device__ __forceinline__ float2 f2(float x, float y) { return make_float2(x, y); }
// acc += w .* h (4 MACs via two packed fma)
__device__ __forceinline__ float2 dot4acc(float4 w, float4 h, float2 acc) {
    acc = ffma2(f2(w.x, w.y), f2(h.x, h.y), acc);
    return ffma2(f2(w.z, w.w), f2(h.z, h.w), acc);
}

__device__ __forceinline__ int read_ps(const int* p) {
    int v = p[0];
    if (v < 0 || v > 1000000) v = (int)__int_as_float(v);
    return v;
}

// ---------------------------------------------------------------------------
// Pass 1: pre[t][b][j] = sum_k x[b][t][k] * W_ih[j][k] + b_ih[j] + b_hh[j]
// For t > ps only k in [16,64) contribute (first 16 are autoregressive).
// ---------------------------------------------------------------------------
__global__ void __launch_bounds__(256) precompute_kernel(
    const float* __restrict__ x, const float* __restrict__ W_ih,
    const float* __restrict__ b_ih, const float* __restrict__ b_hh,
    const int* __restrict__ psp)
{
    __shared__ float xs[32][DIN];
    const int t   = blockIdx.y;
    const int b0  = blockIdx.x * 32;
    const int tid = threadIdx.x;
    const int j   = tid;

    for (int idx = tid; idx < 32 * DIN; idx += 256) {
        int r = idx >> 6, k = idx & 63;
        xs[r][k] = x[((size_t)(b0 + r) * S_LEN + t) * DIN + k];
    }

    float4 wreg[DIN / 4];
    {
        const float4* wrow = reinterpret_cast<const float4*>(W_ih + (size_t)j * DIN);
        #pragma unroll
        for (int i = 0; i < DIN / 4; i++) wreg[i] = wrow[i];
    }
    const float bias = b_ih[j] + b_hh[j];
    const int ps = read_ps(psp);
    const bool full = (t <= ps);
    __syncthreads();

    for (int b = 0; b < 32; b++) {
        const float4* xb = reinterpret_cast<const float4*>(xs[b]);
        float2 acc = f2(bias, 0.f);
        #pragma unroll
        for (int i = 4; i < DIN / 4; i++) acc = dot4acc(wreg[i], xb[i], acc);
        if (full) {
            #pragma unroll
            for (int i = 0; i < 4; i++) acc = dot4acc(wreg[i], xb[i], acc);
        }
        g_pre[((size_t)t * B_SZ + (b0 + b)) * H_DIM + j] = acc.x + acc.y;
    }
}

// ---------------------------------------------------------------------------
// Pass 2: persistent recurrence. 128 blocks x 256 threads, 2 batch rows/block.
// k-split GEMV: warp w -> kh = w&1 (k half), jg = w>>1 (64-j group).
// Thread owns outputs j0 = jg*64+lane (weights in REGS) and j1 = j0+32
// (weights streamed from smem), over k in [kh*128, kh*128+128).
// ---------------------------------------------------------------------------
struct __align__(16) Smem {
    float4 whh4[2][32][128];     // 131072 B : W_hh[j1][kh*128+4i..] at [kh][i][jg*32+l]
    float4 w1p4[4][16][64];      //  65536 B : W1[m][c*64+4i..] at [c][i][m]
    float4 w2p4[16][64];         //  16384 B : W2[m][4i..] at [i][m]
    float4 w34 [16][16];         //   4096 B : W3[m][4i..] at [i][m]
    float  hp  [2][2][H_DIM];    //   8192 B : double-buffered hidden state
    union {                      //   4096 B (phase-disjoint alias)
        float2 redh[2][H_DIM];                   // P1->P3: [kh][j] = (row0,row1)
        struct { float2 red2[4][MLPH];           // P5->P7: [c][m] = (row0,row1)
                 float  h1s [2][MLPH]; } mlp;    // P7->P9
    } u;
    float  h2s [2][MLPH];        //    512 B : P9->P11 (NOT aliased: P11 overlaps next P1)
    float  o_sm[2][DOUT];        //    128 B : previous output (AR feedback)
    float  b1s[MLPH], b2s[MLPH], b3s[DOUT];
};

__global__ void __launch_bounds__(256, 1) rnn_kernel(
    const float* __restrict__ W_hh, const float* __restrict__ W_ih,
    const float* __restrict__ W1, const float* __restrict__ b1,
    const float* __restrict__ W2, const float* __restrict__ b2,
    const float* __restrict__ W3, const float* __restrict__ b3,
    const int* __restrict__ psp, float* __restrict__ out)
{
    extern __shared__ char smraw[];
    Smem& sm = *reinterpret_cast<Smem*>(smraw);
    const int tid = threadIdx.x;
    const int l   = tid & 31;
    const int w   = tid >> 5;
    const int kh  = w & 1;
    const int jg  = w >> 1;
    const int j0  = jg * 64 + l;
    const int j1  = j0 + 32;
    const int kb  = kh * 128;
    const int b0  = blockIdx.x * 2;
    const int ps  = read_ps(psp);

    // ---- register weights: W_hh[j0][kb..kb+128) ----
    float4 wreg4[32];
    {
        const float4* row = reinterpret_cast<const float4*>(W_hh + (size_t)j0 * H_DIM + kb);
        #pragma unroll
        for (int i = 0; i < 32; i++) wreg4[i] = row[i];
    }
    // ---- AR weights for finalize phase: W_ih[tid][0..16) ----
    float4 waP3[4];
    {
        const float4* row = reinterpret_cast<const float4*>(W_ih + (size_t)tid * DIN);
        #pragma unroll
        for (int i = 0; i < 4; i++) waP3[i] = row[i];
    }
    // ---- stage smem weights ----
    {
        const float4* row = reinterpret_cast<const float4*>(W_hh + (size_t)j1 * H_DIM + kb);
        #pragma unroll
        for (int i = 0; i < 32; i++) sm.whh4[kh][i][jg * 32 + l] = row[i];
    }
    for (int idx = tid; idx < 4096; idx += 256) {           // W1: 4096 float4
        int c = idx >> 10, i = (idx >> 6) & 15, m = idx & 63;
        sm.w1p4[c][i][m] = *reinterpret_cast<const float4*>(W1 + (size_t)m * H_DIM + c * 64 + 4 * i);
    }
    for (int idx = tid; idx < 1024; idx += 256) {           // W2: 1024 float4
        int i = idx >> 6, m = idx & 63;
        sm.w2p4[i][m] = *reinterpret_cast<const float4*>(W2 + (size_t)m * MLPH + 4 * i);
    }
    if (tid < 256) {                                        // W3: 256 float4
        int i = tid >> 4, m = tid & 15;
        sm.w34[i][m] = *reinterpret_cast<const float4*>(W3 + (size_t)m * MLPH + 4 * i);
    }
    if (tid < MLPH) { sm.b1s[tid] = b1[tid]; sm.b2s[tid] = b2[tid]; }
    if (tid < DOUT) sm.b3s[tid] = b3[tid];
    sm.hp[0][0][tid] = 0.f;
    sm.hp[0][1][tid] = 0.f;
    if (tid < 2 * DOUT) sm.o_sm[tid >> 4][tid & 15] = 0.f;
    __syncthreads();

    // pre[] prefetch (kh==0 warps only own the bias/pre injection)
    float p00 = 0.f, p01 = 0.f, p10 = 0.f, p11 = 0.f;
    if (kh == 0) {
        p00 = g_pre[((size_t)0 * B_SZ + b0) * H_DIM + j0];
        p01 = g_pre[((size_t)0 * B_SZ + b0) * H_DIM + j1];
        p10 = g_pre[((size_t)0 * B_SZ + b0 + 1) * H_DIM + j0];
        p11 = g_pre[((size_t)0 * B_SZ + b0 + 1) * H_DIM + j1];
    }

    int cur = 0;
    for (int t = 0; t < S_LEN; t++) {
        const int nxt = cur ^ 1;

        // ================= P1: GEMV partials (k-split) =================
        float2 a00 = f2(0.f, 0.f), a10 = a00, a01 = a00, a11 = a00;
        if (kh == 0) { a00.x = p00; a10.x = p10; a01.x = p01; a11.x = p11; }
        if (kh == 0 && t + 1 < S_LEN) {   // prefetch next step's pre
            p00 = g_pre[((size_t)(t + 1) * B_SZ + b0) * H_DIM + j0];
            p01 = g_pre[((size_t)(t + 1) * B_SZ + b0) * H_DIM + j1];
            p10 = g_pre[((size_t)(t + 1) * B_SZ + b0 + 1) * H_DIM + j0];
            p11 = g_pre[((size_t)(t + 1) * B_SZ + b0 + 1) * H_DIM + j1];
        }
        {
            const float4* hb0 = reinterpret_cast<const float4*>(&sm.hp[cur][0][kb]);
            const float4* hb1 = reinterpret_cast<const float4*>(&sm.hp[cur][1][kb]);
            const float4* wsm = &sm.whh4[kh][0][jg * 32 + l];
            #pragma unroll
            for (int i = 0; i < 32; i++) {
                float4 h0 = hb0[i], h1 = hb1[i];
                float4 w0 = wreg4[i];
                float4 w1v = wsm[(size_t)i * 128];
                a00 = dot4acc(w0, h0, a00);
                a10 = dot4acc(w0, h1, a10);
                a01 = dot4acc(w1v, h0, a01);
                a11 = dot4acc(w1v, h1, a11);
            }
        }
        sm.u.redh[kh][j0] = f2(a00.x + a00.y, a10.x + a10.y);
        sm.u.redh[kh][j1] = f2(a01.x + a01.y, a11.x + a11.y);
        __syncthreads();                                   // A

        // ================= P3: finalize h (+AR) =================
        {
            float2 r0 = sm.u.redh[0][tid], r1 = sm.u.redh[1][tid];
            float s0 = r0.x + r1.x, s1 = r0.y + r1.y;
            if (t > ps) {
                const float4* o0 = reinterpret_cast<const float4*>(sm.o_sm[0]);
                const float4* o1 = reinterpret_cast<const float4*>(sm.o_sm[1]);
                float2 q0 = f2(0.f, 0.f), q1 = q0;
                #pragma unroll
                for (int i = 0; i < 4; i++) {
                    q0 = dot4acc(waP3[i], o0[i], q0);
                    q1 = dot4acc(waP3[i], o1[i], q1);
                }
                s0 += q0.x + q0.y; s1 += q1.x + q1.y;
            }
            sm.hp[nxt][0][tid] = tanhf(s0);
            sm.hp[nxt][1][tid] = tanhf(s1);
        }
        __syncthreads();                                   // B

        // ================= P5: MLP1 partials =================
        {
            const int m = tid & 63, c = tid >> 6;
            const float4* g0 = reinterpret_cast<const float4*>(&sm.hp[nxt][0][c * 64]);
            const float4* g1 = reinterpret_cast<const float4*>(&sm.hp[nxt][1][c * 64]);
            float2 s0 = f2(0.f, 0.f), s1 = s0;
            #pragma unroll
            for (int i = 0; i < 16; i++) {
                float4 wv = sm.w1p4[c][i][m];
                s0 = dot4acc(wv, g0[i], s0);
                s1 = dot4acc(wv, g1[i], s1);
            }
            sm.u.mlp.red2[c][m] = f2(s0.x + s0.y, s1.x + s1.y);
        }
        __syncthreads();                                   // C

        // ================= P7: reduce + relu -> h1 =================
        if (tid < 128) {
            const int b = tid >> 6, m = tid & 63;
            const float* rp = reinterpret_cast<const float*>(sm.u.mlp.red2);
            float s = rp[m * 2 + b] + rp[(64 + m) * 2 + b] +
                      rp[(128 + m) * 2 + b] + rp[(192 + m) * 2 + b];
            sm.u.mlp.h1s[b][m] = fmaxf(s + sm.b1s[m], 0.f);
        }
        __syncthreads();                                   // D

        // ================= P9: MLP2 =================
        if (tid < 128) {
            const int b = tid >> 6, m = tid & 63;
            const float4* g = reinterpret_cast<const float4*>(sm.u.mlp.h1s[b]);
            float2 acc = f2(0.f, 0.f);
            #pragma unroll
            for (int i = 0; i < 16; i++) acc = dot4acc(sm.w2p4[i][m], g[i], acc);
            sm.h2s[b][m] = fmaxf(acc.x + acc.y + sm.b2s[m], 0.f);
        }
        __syncthreads();                                   // E

        // ======== P11: MLP3 + out (overlaps next P1 for other threads) ========
        if (tid < 32) {
            const int b = tid >> 4, m = tid & 15;
            const float4* g = reinterpret_cast<const float4*>(sm.h2s[b]);
            float2 acc = f2(0.f, 0.f);
            #pragma unroll
            for (int i = 0; i < 16; i++) acc = dot4acc(sm.w34[i][m], g[i], acc);
            float o = acc.x + acc.y + sm.b3s[m];
            sm.o_sm[b][m] = o;
            out[((size_t)(b0 + b) * S_LEN + t) * DOUT + m] = o;
        }
        cur = nxt;   // no trailing sync: P11's o_sm write is ordered before next
                     // P3's read by barrier A; next P1 touches neither o_sm nor h2s.
    }
}

extern "C" void kernel_launch(void* const* d_in, const int* in_sizes, int n_in,
                              void* d_out, int out_size) {
    const float* x    = (const float*)d_in[0];
    const float* W_ih = (const float*)d_in[1];
    const float* b_ih = (const float*)d_in[2];
    const float* W_hh = (const float*)d_in[3];
    const float* b_hh = (const float*)d_in[4];
    const float* W1   = (const float*)d_in[5];
    const float* b1   = (const float*)d_in[6];
    const float* W2   = (const float*)d_in[7];
    const float* b2   = (const float*)d_in[8];
    const float* W3   = (const float*)d_in[9];
    const float* b3   = (const float*)d_in[10];
    const int*   ps   = (const int*)d_in[11];
    float* out = (float*)d_out;

    precompute_kernel<<<dim3(B_SZ / 32, S_LEN), 256>>>(x, W_ih, b_ih, b_hh, ps);

    static_assert(sizeof(Smem) <= 232448, "smem over budget");
    cudaFuncSetAttribute(rnn_kernel, cudaFuncAttributeMaxDynamicSharedMemorySize,
                         (int)sizeof(Smem));
    rnn_kernel<<<B_SZ / 2, 256, sizeof(Smem)>>>(
        W_hh, W_ih, W1, b1, W2, b2, W3, b3, ps, out);
}

// round 5
// speedup vs baseline: 1.4171x; 1.1126x over previous
#include <cuda_runtime.h>
#include <string.h>

#define S_LEN 512
#define B_SZ  256
#define DIN   64
#define H_DIM 256
#define MLPH  64
#define DOUT  16

// 134MB scratch for precomputed input projections: pre[t][b][j]
__device__ float g_pre[(size_t)S_LEN * B_SZ * H_DIM];

__device__ __forceinline__ float2 ffma2(float2 a, float2 b, float2 c) {
    unsigned long long ua, ub, uc, ur;
    memcpy(&ua, &a, 8); memcpy(&ub, &b, 8); memcpy(&uc, &c, 8);
    asm("fma.rn.f32x2 %0, %1, %2, %3;" : "=l"(ur) : "l"(ua), "l"(ub), "l"(uc));
    float2 r; memcpy(&r, &ur, 8);
    return r;
}
__device__ __forceinline__ float2 f2(float x, float y) { return make_float2(x, y); }
__device__ __forceinline__ float2 dot4acc(float4 w, float4 h, float2 acc) {
    acc = ffma2(f2(w.x, w.y), f2(h.x, h.y), acc);
    return ffma2(f2(w.z, w.w), f2(h.z, h.w), acc);
}

__device__ __forceinline__ int read_ps(const int* p) {
    int v = p[0];
    if (v < 0 || v > 1000000) v = (int)__int_as_float(v);
    return v;
}

// ---------------------------------------------------------------------------
// Pass 1: pre[t][b][j] = sum_k x[b][t][k] * W_ih[j][k] + b_ih[j] + b_hh[j]
// For t > ps only k in [16,64) contribute. 2 timesteps per block.
// ---------------------------------------------------------------------------
__global__ void __launch_bounds__(256) precompute_kernel(
    const float* __restrict__ x, const float* __restrict__ W_ih,
    const float* __restrict__ b_ih, const float* __restrict__ b_hh,
    const int* __restrict__ psp)
{
    __shared__ float xs[2][32][DIN];
    const int t0  = blockIdx.y * 2;
    const int b0  = blockIdx.x * 32;
    const int tid = threadIdx.x;
    const int j   = tid;

    for (int idx = tid; idx < 2 * 32 * DIN; idx += 256) {
        int tt = idx >> 11, r = (idx >> 6) & 31, k = idx & 63;
        xs[tt][r][k] = x[((size_t)(b0 + r) * S_LEN + t0 + tt) * DIN + k];
    }

    float4 wreg[DIN / 4];
    {
        const float4* wrow = reinterpret_cast<const float4*>(W_ih + (size_t)j * DIN);
        #pragma unroll
        for (int i = 0; i < DIN / 4; i++) wreg[i] = wrow[i];
    }
    const float bias = b_ih[j] + b_hh[j];
    const int ps = read_ps(psp);
    __syncthreads();

    #pragma unroll
    for (int tt = 0; tt < 2; tt++) {
        const bool full = (t0 + tt <= ps);
        for (int b = 0; b < 32; b++) {
            const float4* xb = reinterpret_cast<const float4*>(xs[tt][b]);
            float2 acc = f2(bias, 0.f);
            #pragma unroll
            for (int i = 4; i < DIN / 4; i++) acc = dot4acc(wreg[i], xb[i], acc);
            if (full) {
                #pragma unroll
                for (int i = 0; i < 4; i++) acc = dot4acc(wreg[i], xb[i], acc);
            }
            g_pre[((size_t)(t0 + tt) * B_SZ + (b0 + b)) * H_DIM + j] = acc.x + acc.y;
        }
    }
}

// ---------------------------------------------------------------------------
// Pass 2: persistent recurrence. 128 blocks x 256 threads, 2 batch rows/block.
// Software-pipelined: iteration t computes (on h_{t-1} held in sm.hp)
//   - GEMV partials for h_t
//   - fused MLP1 partials -> MLP chain -> o_{t-1}, stored to out[t-1]
//   - then finalizes h_t = tanh(pre_t + GEMV + AR(o_{t-1}))
// Loop runs S_LEN+1 iterations; the last one only emits o_{S-1}.
// ---------------------------------------------------------------------------
struct __align__(16) Smem {
    float4 whh4[2][32][128];   // 131072 : W_hh[j1][kh*128+4i..] at [kh][i][jg*32+l]
    float4 w1s [2][32][64];    //  65536 : W1[m][kh*128+4i..] at [kh][i][m]
    float4 w2p4[16][64];       //  16384 : W2[m][4i..] at [i][m]
    float4 w34 [16][16];       //   4096 : W3[m][4i..] at [i][m]
    float  hp  [2][H_DIM];     //   2048 : hidden state (single buffer) [row][j]
    float2 redh[2][H_DIM];     //   4096 : GEMV partials [kh][j] = (row0,row1)
    float  red2[2][MLPH][2];   //   1024 : MLP1 partials [kh][m][row]
    float  h1s [2][MLPH];      //    512 : [row][m]
    float  h2s [2][MLPH];      //    512
    float  o_sm[2][DOUT];      //    128
    float  b1s[MLPH], b2s[MLPH], b3s[DOUT];
};

__global__ void __launch_bounds__(256, 1) rnn_kernel(
    const float* __restrict__ W_hh, const float* __restrict__ W_ih,
    const float* __restrict__ W1, const float* __restrict__ b1,
    const float* __restrict__ W2, const float* __restrict__ b2,
    const float* __restrict__ W3, const float* __restrict__ b3,
    const int* __restrict__ psp, float* __restrict__ out)
{
    extern __shared__ char smraw[];
    Smem& sm = *reinterpret_cast<Smem*>(smraw);
    const int tid = threadIdx.x;
    const int l   = tid & 31;
    const int w   = tid >> 5;
    const int kh  = w & 1;
    const int jg  = w >> 1;
    const int j0  = jg * 64 + l;
    const int j1  = j0 + 32;
    const int kb  = kh * 128;
    const int b0  = blockIdx.x * 2;
    const int ps  = read_ps(psp);
    // fused MLP1 slot: lane pairs share m, split batch rows
    const int mrow = l & 1;
    const int mm   = jg * 16 + (l >> 1);

    // ---- register weights ----
    float4 wreg4[32];
    {
        const float4* row = reinterpret_cast<const float4*>(W_hh + (size_t)j0 * H_DIM + kb);
        #pragma unroll
        for (int i = 0; i < 32; i++) wreg4[i] = row[i];
    }
    float4 waP[4];   // W_ih[tid][0..16) for AR finalize
    {
        const float4* row = reinterpret_cast<const float4*>(W_ih + (size_t)tid * DIN);
        #pragma unroll
        for (int i = 0; i < 4; i++) waP[i] = row[i];
    }
    // ---- stage smem weights ----
    {
        const float4* row = reinterpret_cast<const float4*>(W_hh + (size_t)j1 * H_DIM + kb);
        #pragma unroll
        for (int i = 0; i < 32; i++) sm.whh4[kh][i][jg * 32 + l] = row[i];
    }
    for (int idx = tid; idx < 4096; idx += 256) {            // W1
        int k2 = idx >> 11, i = (idx >> 6) & 31, m = idx & 63;
        sm.w1s[k2][i][m] = *reinterpret_cast<const float4*>(W1 + (size_t)m * H_DIM + k2 * 128 + 4 * i);
    }
    for (int idx = tid; idx < 1024; idx += 256) {            // W2
        int i = idx >> 6, m = idx & 63;
        sm.w2p4[i][m] = *reinterpret_cast<const float4*>(W2 + (size_t)m * MLPH + 4 * i);
    }
    if (tid < 256) {                                         // W3
        int i = tid >> 4, m = tid & 15;
        sm.w34[i][m] = *reinterpret_cast<const float4*>(W3 + (size_t)m * MLPH + 4 * i);
    }
    if (tid < MLPH) { sm.b1s[tid] = b1[tid]; sm.b2s[tid] = b2[tid]; }
    if (tid < DOUT) sm.b3s[tid] = b3[tid];
    sm.hp[0][tid] = 0.f;
    sm.hp[1][tid] = 0.f;
    if (tid < 2 * DOUT) sm.o_sm[tid >> 4][tid & 15] = 0.f;
    __syncthreads();

    // per-thread pre prefetch (j = tid, both rows): pn holds pre[t] at iter t
    float pn0 = g_pre[((size_t)0 * B_SZ + b0) * H_DIM + tid];
    float pn1 = g_pre[((size_t)0 * B_SZ + b0 + 1) * H_DIM + tid];

    float s0 = 0.f, s1 = 0.f;
    for (int t = 0; t <= S_LEN; t++) {
        // ========== Ph1: GEMV partials (for h_t) + MLP1 partials (on h_{t-1}) ==========
        {
            float2 a00 = f2(0.f, 0.f), a10 = a00, a01 = a00, a11 = a00, ms = a00;
            const float4* hb0 = reinterpret_cast<const float4*>(&sm.hp[0][kb]);
            const float4* hb1 = reinterpret_cast<const float4*>(&sm.hp[1][kb]);
            const float4* wsm = &sm.whh4[kh][0][jg * 32 + l];
            const float4* wmp = &sm.w1s[kh][0][mm];
            #pragma unroll
            for (int i = 0; i < 32; i++) {
                float4 h0 = hb0[i], h1 = hb1[i];
                float4 w0 = wreg4[i];
                float4 wv = wsm[(size_t)i * 128];
                a00 = dot4acc(w0, h0, a00);
                a10 = dot4acc(w0, h1, a10);
                a01 = dot4acc(wv, h0, a01);
                a11 = dot4acc(wv, h1, a11);
                float4 wm = wmp[(size_t)i * 64];
                float4 hm;
                hm.x = mrow ? h1.x : h0.x; hm.y = mrow ? h1.y : h0.y;
                hm.z = mrow ? h1.z : h0.z; hm.w = mrow ? h1.w : h0.w;
                ms = dot4acc(wm, hm, ms);
            }
            sm.redh[kh][j0] = f2(a00.x + a00.y, a10.x + a10.y);
            sm.redh[kh][j1] = f2(a01.x + a01.y, a11.x + a11.y);
            sm.red2[kh][mm][mrow] = ms.x + ms.y;
        }
        __syncthreads();                                    // A

        // ========== Ph2: stash GEMV sums + MLP1 reduce ==========
        {
            float2 r0 = sm.redh[0][tid], r1 = sm.redh[1][tid];
            s0 = r0.x + r1.x + pn0;
            s1 = r0.y + r1.y + pn1;
            if (t + 1 < S_LEN) {
                pn0 = g_pre[((size_t)(t + 1) * B_SZ + b0) * H_DIM + tid];
                pn1 = g_pre[((size_t)(t + 1) * B_SZ + b0 + 1) * H_DIM + tid];
            }
            if (tid < 128) {
                const int row = tid & 1, m = tid >> 1;
                float v = sm.red2[0][m][row] + sm.red2[1][m][row] + sm.b1s[m];
                sm.h1s[row][m] = fmaxf(v, 0.f);
            }
        }
        __syncthreads();                                    // B

        // ========== Ph3: MLP2 ==========
        if (tid < 128) {
            const int row = tid & 1, m = tid >> 1;
            const float4* g = reinterpret_cast<const float4*>(sm.h1s[row]);
            float2 acc = f2(0.f, 0.f);
            #pragma unroll
            for (int i = 0; i < 16; i++) acc = dot4acc(sm.w2p4[i][m], g[i], acc);
            sm.h2s[row][m] = fmaxf(acc.x + acc.y + sm.b2s[m], 0.f);
        }
        __syncthreads();                                    // C

        // ========== Ph4: MLP3 -> o_{t-1}; store out[t-1] ==========
        if (tid < 32) {
            const int b = tid >> 4, m = tid & 15;
            const float4* g = reinterpret_cast<const float4*>(sm.h2s[b]);
            float2 acc = f2(0.f, 0.f);
            #pragma unroll
            for (int i = 0; i < 16; i++) acc = dot4acc(sm.w34[i][m], g[i], acc);
            float o = acc.x + acc.y + sm.b3s[m];
            sm.o_sm[b][m] = o;
            if (t > 0)
                out[((size_t)(b0 + b) * S_LEN + (t - 1)) * DOUT + m] = o;
        }
        __syncthreads();                                    // D

        // ========== Ph5: finalize h_t (+AR with o_{t-1}) ==========
        if (t < S_LEN) {
            float aa0 = s0, aa1 = s1;
            if (t > ps && t > 0) {
                const float4* o0 = reinterpret_cast<const float4*>(sm.o_sm[0]);
                const float4* o1 = reinterpret_cast<const float4*>(sm.o_sm[1]);
                float2 q0 = f2(0.f, 0.f), q1 = q0;
                #pragma unroll
                for (int i = 0; i < 4; i++) {
                    q0 = dot4acc(waP[i], o0[i], q0);
                    q1 = dot4acc(waP[i], o1[i], q1);
                }
                aa0 += q0.x + q0.y;
                aa1 += q1.x + q1.y;
            }
            sm.hp[0][tid] = tanhf(aa0);
            sm.hp[1][tid] = tanhf(aa1);
        }
        __syncthreads();                                    // E
    }
}

extern "C" void kernel_launch(void* const* d_in, const int* in_sizes, int n_in,
                              void* d_out, int out_size) {
    const float* x    = (const float*)d_in[0];
    const float* W_ih = (const float*)d_in[1];
    const float* b_ih = (const float*)d_in[2];
    const float* W_hh = (const float*)d_in[3];
    const float* b_hh = (const float*)d_in[4];
    const float* W1   = (const float*)d_in[5];
    const float* b1   = (const float*)d_in[6];
    const float* W2   = (const float*)d_in[7];
    const float* b2   = (const float*)d_in[8];
    const float* W3   = (const float*)d_in[9];
    const float* b3   = (const float*)d_in[10];
    const int*   ps   = (const int*)d_in[11];
    float* out = (float*)d_out;

    precompute_kernel<<<dim3(B_SZ / 32, S_LEN / 2), 256>>>(x, W_ih, b_ih, b_hh, ps);

    static_assert(sizeof(Smem) <= 232448, "smem over budget");
    cudaFuncSetAttribute(rnn_kernel, cudaFuncAttributeMaxDynamicSharedMemorySize,
                         (int)sizeof(Smem));
    rnn_kernel<<<B_SZ / 2, 256, sizeof(Smem)>>>(
        W_hh, W_ih, W1, b1, W2, b2, W3, b3, ps, out);
}